// round 1
// baseline (speedup 1.0000x reference)
#include <cuda_runtime.h>
#include <math.h>

#define BATCH 8192
#define SEQ 2
#define EMB 1024
#define MROWS (BATCH*SEQ)   // 16384
#define HID 2048

// ---------------- scratch (device globals; no allocs allowed) ----------------
__device__ float g_xs  [MROWS*EMB];
__device__ float g_q   [MROWS*EMB];
__device__ float g_k   [MROWS*EMB];
__device__ float g_v   [MROWS*EMB];
__device__ float g_cc  [MROWS*EMB];
__device__ float g_out1[MROWS*EMB];
__device__ float g_ln2 [MROWS*EMB];
__device__ float g_h   [2L*BATCH*HID];

// ---------------- LayerNorm over the joint (S,E)=2048 slice ----------------
// one block per batch element b; x slice = x[b*2048 .. +2048)
__global__ void __launch_bounds__(256) ln_kernel(
    const float* __restrict__ x, const float* __restrict__ w,
    const float* __restrict__ bb, float* __restrict__ y)
{
    __shared__ float red[16];
    const long base = (long)blockIdx.x * 2048;
    const float4* xp = (const float4*)(x + base);
    int t = threadIdx.x;
    float4 v0 = xp[t];
    float4 v1 = xp[t + 256];
    float s  = v0.x+v0.y+v0.z+v0.w + v1.x+v1.y+v1.z+v1.w;
    float s2 = v0.x*v0.x+v0.y*v0.y+v0.z*v0.z+v0.w*v0.w
             + v1.x*v1.x+v1.y*v1.y+v1.z*v1.z+v1.w*v1.w;
    // block reduce (sum, sumsq)
    #pragma unroll
    for (int o = 16; o; o >>= 1) {
        s  += __shfl_xor_sync(0xffffffffu, s,  o);
        s2 += __shfl_xor_sync(0xffffffffu, s2, o);
    }
    int warp = t >> 5, lane = t & 31;
    if (lane == 0) { red[warp] = s; red[warp + 8] = s2; }
    __syncthreads();
    if (warp == 0) {
        float a = (lane < 8) ? red[lane] : 0.f;
        float b2 = (lane < 8) ? red[lane + 8] : 0.f;
        #pragma unroll
        for (int o = 4; o; o >>= 1) {
            a  += __shfl_xor_sync(0xffffffffu, a,  o);
            b2 += __shfl_xor_sync(0xffffffffu, b2, o);
        }
        if (lane == 0) { red[0] = a; red[1] = b2; }
    }
    __syncthreads();
    float mean = red[0] * (1.f/2048.f);
    float var  = red[1] * (1.f/2048.f) - mean*mean;
    float rs   = rsqrtf(var + 1e-5f);

    const float4* wp = (const float4*)w;
    const float4* bp = (const float4*)bb;
    float4* yp = (float4*)(y + base);
    #pragma unroll
    for (int r = 0; r < 2; r++) {
        int i = t + r*256;
        float4 xv = (r == 0) ? v0 : v1;
        float4 wv = wp[i], bv = bp[i], o;
        o.x = (xv.x - mean)*rs*wv.x + bv.x;
        o.y = (xv.y - mean)*rs*wv.y + bv.y;
        o.z = (xv.z - mean)*rs*wv.z + bv.z;
        o.w = (xv.w - mean)*rs*wv.w + bv.w;
        yp[i] = o;
    }
}

// ---------------- tiny attention: per (b,h) 2x2 softmax mix ----------------
// head h occupies columns {d*16+h : d in [0,64)} of the 1024-wide projection.
// one block per b, one warp per head (16 warps = 512 threads).
// smem padded: element j stored at j + (j>>4)  (stride-16 access -> stride-17 => conflict-free)
__global__ void __launch_bounds__(512) attn_kernel(
    const float* __restrict__ q, const float* __restrict__ k,
    const float* __restrict__ v, float* __restrict__ cc)
{
    __shared__ float sq[2176], sk[2176], sv[2176];
    const long base = (long)blockIdx.x * 2048;
    // load 3*2048 floats, padded scatter
    for (int i = threadIdx.x; i < 512; i += 512) {
        float4 a = ((const float4*)(q + base))[i];
        float4 b = ((const float4*)(k + base))[i];
        float4 c = ((const float4*)(v + base))[i];
        int j = i*4; int pj = j + (j >> 4);
        sq[pj]=a.x; sq[pj+1]=a.y; sq[pj+2]=a.z; sq[pj+3]=a.w;
        sk[pj]=b.x; sk[pj+1]=b.y; sk[pj+2]=b.z; sk[pj+3]=b.w;
        sv[pj]=c.x; sv[pj+1]=c.y; sv[pj+2]=c.z; sv[pj+3]=c.w;
    }
    __syncthreads();
    int h = threadIdx.x >> 5;
    int l = threadIdx.x & 31;
    // padded idx for col c=d*16+h (c<1024): c+(c>>4) = d*17+h ; s=1 row offset: 1024+c -> pad 1024+64=1088
    int i0 = l*17 + h;            // s=0, d=l
    int i1 = (l+32)*17 + h;       // s=0, d=l+32
    int j0 = 1088 + i0;           // s=1, d=l
    int j1 = 1088 + i1;           // s=1, d=l+32
    float q00=sq[i0], q01=sq[i1], q10=sq[j0], q11=sq[j1];
    float k00=sk[i0], k01=sk[i1], k10=sk[j0], k11=sk[j1];
    float s00 = q00*k00 + q01*k01;
    float s01 = q00*k10 + q01*k11;
    float s10 = q10*k00 + q11*k01;
    float s11 = q10*k10 + q11*k11;
    #pragma unroll
    for (int o = 16; o; o >>= 1) {
        s00 += __shfl_xor_sync(0xffffffffu, s00, o);
        s01 += __shfl_xor_sync(0xffffffffu, s01, o);
        s10 += __shfl_xor_sync(0xffffffffu, s10, o);
        s11 += __shfl_xor_sync(0xffffffffu, s11, o);
    }
    const float inv = 0.125f;  // 1/sqrt(64)
    s00*=inv; s01*=inv; s10*=inv; s11*=inv;
    float m0 = fmaxf(s00, s01), m1 = fmaxf(s10, s11);
    float e00 = __expf(s00-m0), e01 = __expf(s01-m0);
    float e10 = __expf(s10-m1), e11 = __expf(s11-m1);
    float r0 = 1.f/(e00+e01),  r1 = 1.f/(e10+e11);
    float p00=e00*r0, p01=e01*r0, p10=e10*r1, p11=e11*r1;

    float v00=sv[i0], v01=sv[i1], v10=sv[j0], v11=sv[j1];
    int c0 = l*16 + h, c1 = (l+32)*16 + h;
    cc[base        + c0] = p00*v00 + p01*v10;
    cc[base        + c1] = p00*v01 + p01*v11;
    cc[base + 1024 + c0] = p10*v00 + p11*v10;
    cc[base + 1024 + c1] = p10*v01 + p11*v11;
}

// ---------------- SGEMM: C[m,n] = sum_k A[m,k] * W[n,k]  (+epilogue) ----------------
// 128x128 tile, BK=8, 256 threads, 8x8 per thread.
// epi: 0 = none ; 1 = +addsrc ; 2 = tanh(acc+bias) ; 3 = tanh(acc+bias)+addsrc
__global__ void __launch_bounds__(256, 2) gemm_nt(
    const float* __restrict__ A, int lda,
    const float* __restrict__ W,              // N x K, row-major (ldw = Kdim)
    const float* __restrict__ bias,
    float* __restrict__ C, int ldc,
    const float* __restrict__ addsrc, int ldadd,
    int Kdim, int epi)
{
    __shared__ float As[8][128];
    __shared__ float Bs[8][128];
    const int tid  = threadIdx.x;
    const int bm   = blockIdx.y * 128;
    const int bn   = blockIdx.x * 128;
    const int lrow = tid >> 1;
    const int lcol = (tid & 1) * 4;
    const float* Aptr = A + (long)(bm + lrow) * lda  + lcol;
    const float* Wptr = W + (long)(bn + lrow) * Kdim + lcol;
    const int tx = tid & 15, ty = tid >> 4;

    float acc[8][8];
    #pragma unroll
    for (int i = 0; i < 8; i++)
        #pragma unroll
        for (int j = 0; j < 8; j++) acc[i][j] = 0.f;

    for (int k0 = 0; k0 < Kdim; k0 += 8) {
        float4 a4 = *(const float4*)(Aptr + k0);
        float4 b4 = *(const float4*)(Wptr + k0);
        As[lcol+0][lrow]=a4.x; As[lcol+1][lrow]=a4.y; As[lcol+2][lrow]=a4.z; As[lcol+3][lrow]=a4.w;
        Bs[lcol+0][lrow]=b4.x; Bs[lcol+1][lrow]=b4.y; Bs[lcol+2][lrow]=b4.z; Bs[lcol+3][lrow]=b4.w;
        __syncthreads();
        #pragma unroll
        for (int kk = 0; kk < 8; kk++) {
            float a[8], b[8];
            *(float4*)(a  ) = *(const float4*)&As[kk][ty*8  ];
            *(float4*)(a+4) = *(const float4*)&As[kk][ty*8+4];
            *(float4*)(b  ) = *(const float4*)&Bs[kk][tx*8  ];
            *(float4*)(b+4) = *(const float4*)&Bs[kk][tx*8+4];
            #pragma unroll
            for (int i = 0; i < 8; i++)
                #pragma unroll
                for (int j = 0; j < 8; j++)
                    acc[i][j] = fmaf(a[i], b[j], acc[i][j]);
        }
        __syncthreads();
    }

    float bv[8];
    if (epi >= 2) {
        #pragma unroll
        for (int j = 0; j < 8; j++) bv[j] = bias[bn + tx*8 + j];
    }
    #pragma unroll
    for (int i = 0; i < 8; i++) {
        long m = bm + ty*8 + i;
        float* crow = C + m * (long)ldc + bn + tx*8;
        const float* arow = addsrc + m * (long)ldadd + bn + tx*8;
        #pragma unroll
        for (int j = 0; j < 8; j += 4) {
            float4 r;
            r.x = acc[i][j+0]; r.y = acc[i][j+1]; r.z = acc[i][j+2]; r.w = acc[i][j+3];
            if (epi >= 2) {
                r.x = tanhf(r.x + bv[j+0]); r.y = tanhf(r.y + bv[j+1]);
                r.z = tanhf(r.z + bv[j+2]); r.w = tanhf(r.w + bv[j+3]);
            }
            if (epi == 1 || epi == 3) {
                float4 av = *(const float4*)(arow + j);
                r.x += av.x; r.y += av.y; r.z += av.z; r.w += av.w;
            }
            *(float4*)(crow + j) = r;
        }
    }
}

// ---------------- host ----------------
static float *p_xs, *p_q, *p_k, *p_v, *p_cc, *p_out1, *p_ln2, *p_h;
static bool g_init = false;

extern "C" void kernel_launch(void* const* d_in, const int* in_sizes, int n_in,
                              void* d_out, int out_size)
{
    if (!g_init) {
        cudaGetSymbolAddress((void**)&p_xs,   g_xs);
        cudaGetSymbolAddress((void**)&p_q,    g_q);
        cudaGetSymbolAddress((void**)&p_k,    g_k);
        cudaGetSymbolAddress((void**)&p_v,    g_v);
        cudaGetSymbolAddress((void**)&p_cc,   g_cc);
        cudaGetSymbolAddress((void**)&p_out1, g_out1);
        cudaGetSymbolAddress((void**)&p_ln2,  g_ln2);
        cudaGetSymbolAddress((void**)&p_h,    g_h);
        g_init = true;
    }
    const float* input = (const float*)d_in[0];
    const float* Wq    = (const float*)d_in[1];
    const float* Wk    = (const float*)d_in[2];
    const float* Wv    = (const float*)d_in[3];
    const float* Wo    = (const float*)d_in[4];
    const float* ln1w  = (const float*)d_in[5];
    const float* ln1b  = (const float*)d_in[6];
    const float* ln2w  = (const float*)d_in[7];
    const float* ln2b  = (const float*)d_in[8];
    const float* f1w1  = (const float*)d_in[9];
    const float* f1b1  = (const float*)d_in[10];
    const float* f1w2  = (const float*)d_in[11];
    const float* f1b2  = (const float*)d_in[12];
    const float* f2w1  = (const float*)d_in[13];
    const float* f2b1  = (const float*)d_in[14];
    const float* f2w2  = (const float*)d_in[15];
    const float* f2b2  = (const float*)d_in[16];
    float* out = (float*)d_out;

    dim3 blk(256);

    // 1. LN1
    ln_kernel<<<BATCH, 256>>>(input, ln1w, ln1b, p_xs);

    // 2. QKV projections: (16384 x 1024) @ (1024 x 1024)^T
    dim3 gq(EMB/128, MROWS/128);
    gemm_nt<<<gq, blk>>>(p_xs, EMB, Wq, nullptr, p_q, EMB, nullptr, 0, EMB, 0);
    gemm_nt<<<gq, blk>>>(p_xs, EMB, Wk, nullptr, p_k, EMB, nullptr, 0, EMB, 0);
    gemm_nt<<<gq, blk>>>(p_xs, EMB, Wv, nullptr, p_v, EMB, nullptr, 0, EMB, 0);

    // 3. attention mix -> concat
    attn_kernel<<<BATCH, 512>>>(p_q, p_k, p_v, p_cc);

    // 4. Wo projection + residual: out1 = input + cc @ Wo^T
    gemm_nt<<<gq, blk>>>(p_cc, EMB, Wo, nullptr, p_out1, EMB, input, EMB, EMB, 1);

    // 5. LN2
    ln_kernel<<<BATCH, 256>>>(p_out1, ln2w, ln2b, p_ln2);

    // 6. FFN layer 1 (per s): h_s = tanh(out_s[:,s,:] @ w1^T + b1)   (8192 x 2048, K=1024)
    dim3 gf1(HID/128, BATCH/128);
    gemm_nt<<<gf1, blk>>>(p_ln2,       2*EMB, f1w1, f1b1, p_h,                  HID, nullptr, 0, EMB, 2);
    gemm_nt<<<gf1, blk>>>(p_ln2 + EMB, 2*EMB, f2w1, f2b1, p_h + (long)BATCH*HID, HID, nullptr, 0, EMB, 2);

    // 7. FFN layer 2 (per s) + final residual: out[:,s,:] = tanh(h_s @ w2^T + b2) + out1[:,s,:]
    dim3 gf2(EMB/128, BATCH/128);
    gemm_nt<<<gf2, blk>>>(p_h,                  HID, f1w2, f1b2, out,       2*EMB, p_out1,       2*EMB, HID, 3);
    gemm_nt<<<gf2, blk>>>(p_h + (long)BATCH*HID, HID, f2w2, f2b2, out + EMB, 2*EMB, p_out1 + EMB, 2*EMB, HID, 3);
}

// round 5
// speedup vs baseline: 3.0529x; 3.0529x over previous
#include <cuda_runtime.h>
#include <cuda_bf16.h>
#include <cstdint>
#include <math.h>

#define BATCH 8192
#define SEQ 2
#define EMB 1024
#define MROWS (BATCH*SEQ)   // 16384
#define HID 2048
#define ME (MROWS*EMB)      // 16777216
#define HBUF (2L*BATCH*HID) // 33554432

typedef __nv_bfloat16 bf16;
typedef __nv_bfloat162 bf162;
typedef unsigned int u32;

// ---------------- scratch (device globals; no allocs allowed) ----------------
__device__ float g_q   [ME];
__device__ float g_k   [ME];
__device__ float g_v   [ME];
__device__ float g_out1[ME];
__device__ bf16 g_xs_h [ME],  g_xs_l [ME];
__device__ bf16 g_cc_h [ME],  g_cc_l [ME];
__device__ bf16 g_ln2_h[ME],  g_ln2_l[ME];
__device__ bf16 g_h_h  [HBUF],g_h_l  [HBUF];
__device__ bf16 g_wq_h[EMB*EMB],  g_wq_l[EMB*EMB];
__device__ bf16 g_wk_h[EMB*EMB],  g_wk_l[EMB*EMB];
__device__ bf16 g_wv_h[EMB*EMB],  g_wv_l[EMB*EMB];
__device__ bf16 g_wo_h[EMB*EMB],  g_wo_l[EMB*EMB];
__device__ bf16 g_f1w1_h[HID*EMB], g_f1w1_l[HID*EMB];
__device__ bf16 g_f1w2_h[HID*EMB], g_f1w2_l[HID*EMB];
__device__ bf16 g_f2w1_h[HID*EMB], g_f2w1_l[HID*EMB];
__device__ bf16 g_f2w2_h[HID*EMB], g_f2w2_l[HID*EMB];

// ---------------- fp32 -> (hi,lo) bf16 split ----------------
__device__ __forceinline__ void split1(float x, bf16& h, bf16& l) {
    h = __float2bfloat16_rn(x);
    l = __float2bfloat16_rn(x - __bfloat162float(h));
}

__global__ void __launch_bounds__(256) split_kernel(
    const float* __restrict__ x, bf16* __restrict__ hi, bf16* __restrict__ lo, int n4)
{
    int i = blockIdx.x * 256 + threadIdx.x;
    if (i >= n4) return;
    float4 v = ((const float4*)x)[i];
    bf16 h0,l0,h1,l1,h2,l2,h3,l3;
    split1(v.x,h0,l0); split1(v.y,h1,l1); split1(v.z,h2,l2); split1(v.w,h3,l3);
    bf162 ha; ha.x=h0; ha.y=h1; bf162 hb; hb.x=h2; hb.y=h3;
    bf162 la; la.x=l0; la.y=l1; bf162 lb; lb.x=l2; lb.y=l3;
    ((bf162*)hi)[i*2]=ha; ((bf162*)hi)[i*2+1]=hb;
    ((bf162*)lo)[i*2]=la; ((bf162*)lo)[i*2+1]=lb;
}

// ---------------- LayerNorm over joint (S,E)=2048, writes bf16 hi/lo ----------------
__global__ void __launch_bounds__(256) ln_kernel(
    const float* __restrict__ x, const float* __restrict__ w,
    const float* __restrict__ bb, bf16* __restrict__ hi, bf16* __restrict__ lo)
{
    __shared__ float red[16];
    const long base = (long)blockIdx.x * 2048;
    const float4* xp = (const float4*)(x + base);
    int t = threadIdx.x;
    float4 v0 = xp[t];
    float4 v1 = xp[t + 256];
    float s  = v0.x+v0.y+v0.z+v0.w + v1.x+v1.y+v1.z+v1.w;
    float s2 = v0.x*v0.x+v0.y*v0.y+v0.z*v0.z+v0.w*v0.w
             + v1.x*v1.x+v1.y*v1.y+v1.z*v1.z+v1.w*v1.w;
    #pragma unroll
    for (int o = 16; o; o >>= 1) {
        s  += __shfl_xor_sync(0xffffffffu, s,  o);
        s2 += __shfl_xor_sync(0xffffffffu, s2, o);
    }
    int warp = t >> 5, lane = t & 31;
    if (lane == 0) { red[warp] = s; red[warp + 8] = s2; }
    __syncthreads();
    if (warp == 0) {
        float a = (lane < 8) ? red[lane] : 0.f;
        float b2 = (lane < 8) ? red[lane + 8] : 0.f;
        #pragma unroll
        for (int o = 4; o; o >>= 1) {
            a  += __shfl_xor_sync(0xffffffffu, a,  o);
            b2 += __shfl_xor_sync(0xffffffffu, b2, o);
        }
        if (lane == 0) { red[0] = a; red[1] = b2; }
    }
    __syncthreads();
    float mean = red[0] * (1.f/2048.f);
    float var  = red[1] * (1.f/2048.f) - mean*mean;
    float rs   = rsqrtf(var + 1e-5f);

    const float4* wp = (const float4*)w;
    const float4* bp = (const float4*)bb;
    bf162* hp = (bf162*)(hi + base);
    bf162* lp = (bf162*)(lo + base);
    #pragma unroll
    for (int r = 0; r < 2; r++) {
        int i = t + r*256;
        float4 xv = (r == 0) ? v0 : v1;
        float4 wv = wp[i], bv = bp[i];
        float o0 = (xv.x - mean)*rs*wv.x + bv.x;
        float o1 = (xv.y - mean)*rs*wv.y + bv.y;
        float o2 = (xv.z - mean)*rs*wv.z + bv.z;
        float o3 = (xv.w - mean)*rs*wv.w + bv.w;
        bf16 h0,l0,h1,l1,h2,l2,h3,l3;
        split1(o0,h0,l0); split1(o1,h1,l1); split1(o2,h2,l2); split1(o3,h3,l3);
        bf162 ha; ha.x=h0; ha.y=h1; bf162 hb; hb.x=h2; hb.y=h3;
        bf162 la; la.x=l0; la.y=l1; bf162 lb; lb.x=l2; lb.y=l3;
        hp[i*2]=ha; hp[i*2+1]=hb; lp[i*2]=la; lp[i*2+1]=lb;
    }
}

// ---------------- tiny attention: per (b,h) 2x2 softmax mix (fp32 in, bf16 split out) --
__global__ void __launch_bounds__(512) attn_kernel(
    const float* __restrict__ q, const float* __restrict__ k,
    const float* __restrict__ v, bf16* __restrict__ cch, bf16* __restrict__ ccl)
{
    __shared__ float sq[2176], sk[2176], sv[2176];
    const long base = (long)blockIdx.x * 2048;
    for (int i = threadIdx.x; i < 512; i += 512) {
        float4 a = ((const float4*)(q + base))[i];
        float4 b = ((const float4*)(k + base))[i];
        float4 c = ((const float4*)(v + base))[i];
        int j = i*4; int pj = j + (j >> 4);
        sq[pj]=a.x; sq[pj+1]=a.y; sq[pj+2]=a.z; sq[pj+3]=a.w;
        sk[pj]=b.x; sk[pj+1]=b.y; sk[pj+2]=b.z; sk[pj+3]=b.w;
        sv[pj]=c.x; sv[pj+1]=c.y; sv[pj+2]=c.z; sv[pj+3]=c.w;
    }
    __syncthreads();
    int h = threadIdx.x >> 5;
    int l = threadIdx.x & 31;
    int i0 = l*17 + h;
    int i1 = (l+32)*17 + h;
    int j0 = 1088 + i0;
    int j1 = 1088 + i1;
    float q00=sq[i0], q01=sq[i1], q10=sq[j0], q11=sq[j1];
    float k00=sk[i0], k01=sk[i1], k10=sk[j0], k11=sk[j1];
    float s00 = q00*k00 + q01*k01;
    float s01 = q00*k10 + q01*k11;
    float s10 = q10*k00 + q11*k01;
    float s11 = q10*k10 + q11*k11;
    #pragma unroll
    for (int o = 16; o; o >>= 1) {
        s00 += __shfl_xor_sync(0xffffffffu, s00, o);
        s01 += __shfl_xor_sync(0xffffffffu, s01, o);
        s10 += __shfl_xor_sync(0xffffffffu, s10, o);
        s11 += __shfl_xor_sync(0xffffffffu, s11, o);
    }
    const float inv = 0.125f;
    s00*=inv; s01*=inv; s10*=inv; s11*=inv;
    float m0 = fmaxf(s00, s01), m1 = fmaxf(s10, s11);
    float e00 = __expf(s00-m0), e01 = __expf(s01-m0);
    float e10 = __expf(s10-m1), e11 = __expf(s11-m1);
    float r0 = 1.f/(e00+e01),  r1 = 1.f/(e10+e11);
    float p00=e00*r0, p01=e01*r0, p10=e10*r1, p11=e11*r1;

    float v00=sv[i0], v01=sv[i1], v10=sv[j0], v11=sv[j1];
    int c0 = l*16 + h, c1 = (l+32)*16 + h;
    float o00 = p00*v00 + p01*v10;
    float o01 = p00*v01 + p01*v11;
    float o10 = p10*v00 + p11*v10;
    float o11 = p10*v01 + p11*v11;
    bf16 hh, ll;
    split1(o00,hh,ll); cch[base+c0]=hh;        ccl[base+c0]=ll;
    split1(o01,hh,ll); cch[base+c1]=hh;        ccl[base+c1]=ll;
    split1(o10,hh,ll); cch[base+1024+c0]=hh;   ccl[base+1024+c0]=ll;
    split1(o11,hh,ll); cch[base+1024+c1]=hh;   ccl[base+1024+c1]=ll;
}

// ---------------- bf16-split tensor-core GEMM ----------------
// C[m,n] = sum_k A[m,k]*W[n,k], A=Ah+Al, W=Bh+Bl, acc = AhBh + AhBl + AlBh (fp32)
// block 128x128, 8 warps (warp tile 64x32), K-step 16, double-buffered smem.
// epi: 0 C=acc ; 1 C=acc+addsrc ; 2 (Oh,Ol)=split(tanh(acc+bias)) ; 3 C=tanh(acc+bias)+addsrc

#define LDM4(R, addr) \
    asm volatile("ldmatrix.sync.aligned.m8n8.x4.shared.b16 {%0,%1,%2,%3}, [%4];" \
        : "=r"(R[0]),"=r"(R[1]),"=r"(R[2]),"=r"(R[3]) : "r"(addr))

#define MMA(C, A, b0, b1) \
    asm volatile("mma.sync.aligned.m16n8k16.row.col.f32.bf16.bf16.f32 " \
        "{%0,%1,%2,%3},{%4,%5,%6,%7},{%8,%9},{%0,%1,%2,%3};" \
        : "+f"(C[0]),"+f"(C[1]),"+f"(C[2]),"+f"(C[3]) \
        : "r"(A[0]),"r"(A[1]),"r"(A[2]),"r"(A[3]),"r"(b0),"r"(b1))

// smem: 2 stages x 4 buffers(Ah,Al,Bh,Bl) x 128 rows x 48B (16 bf16 + 16B pad)
#define BUF_A_H 0
#define BUF_A_L 6144
#define BUF_B_H 12288
#define BUF_B_L 18432
#define STAGE   24576

__global__ void __launch_bounds__(256, 1) gemm_bf3(
    const bf16* __restrict__ Ah, const bf16* __restrict__ Al, int lda,
    const bf16* __restrict__ Bh, const bf16* __restrict__ Bl, int ldb,
    const float* __restrict__ bias,
    float* __restrict__ C, int ldc,
    const float* __restrict__ addsrc, int ldadd,
    bf16* __restrict__ Oh, bf16* __restrict__ Ol, int ldo,
    int K, int epi)
{
    __shared__ __align__(16) char smem[2*STAGE];
    const int tid = threadIdx.x, warp = tid >> 5, lane = tid & 31;
    const int bm = blockIdx.y * 128, bn = blockIdx.x * 128;
    const int wm = warp >> 2, wn = warp & 3;

    // global staging: each thread loads one 16B chunk per buffer per k-step
    const int ra = tid >> 1, ch = tid & 1;
    const bf16* gAh = Ah + (size_t)(bm + ra) * lda + ch * 8;
    const bf16* gAl = Al + (size_t)(bm + ra) * lda + ch * 8;
    const bf16* gBh = Bh + (size_t)(bn + ra) * ldb + ch * 8;
    const bf16* gBl = Bl + (size_t)(bn + ra) * ldb + ch * 8;
    const int sts_off = ra * 48 + ch * 16;

    // ldmatrix lane offsets
    const u32 sbase = (u32)__cvta_generic_to_shared(smem);
    const int arow = lane & 15, ach = lane >> 4;
    u32 offA[4];
    #pragma unroll
    for (int mt = 0; mt < 4; mt++)
        offA[mt] = (u32)((wm*64 + mt*16 + arow) * 48 + ach * 16);
    const int brow = (lane & 7) + ((lane & 16) >> 1);
    const int bch  = (lane >> 3) & 1;
    u32 offB[2];
    #pragma unroll
    for (int bt = 0; bt < 2; bt++)
        offB[bt] = (u32)(BUF_B_H + (wn*32 + bt*16 + brow) * 48 + bch * 16);

    float c[4][4][4];
    #pragma unroll
    for (int i = 0; i < 4; i++)
        #pragma unroll
        for (int j = 0; j < 4; j++)
            #pragma unroll
            for (int r = 0; r < 4; r++) c[i][j][r] = 0.f;

    // preload k-tile 0
    {
        uint4 a = *(const uint4*)gAh;
        uint4 b = *(const uint4*)gAl;
        uint4 d = *(const uint4*)gBh;
        uint4 e = *(const uint4*)gBl;
        *(uint4*)(smem + BUF_A_H + sts_off) = a;
        *(uint4*)(smem + BUF_A_L + sts_off) = b;
        *(uint4*)(smem + BUF_B_H + sts_off) = d;
        *(uint4*)(smem + BUF_B_L + sts_off) = e;
    }
    __syncthreads();

    const int nk = K >> 4;
    #pragma unroll 1
    for (int kt = 0; kt < nk; kt++) {
        const u32 st = (u32)((kt & 1) * STAGE);
        uint4 nA, nB, nC, nD;
        const bool more = (kt + 1 < nk);
        if (more) {
            int ko = (kt + 1) * 16;
            nA = *(const uint4*)(gAh + ko);
            nB = *(const uint4*)(gAl + ko);
            nC = *(const uint4*)(gBh + ko);
            nD = *(const uint4*)(gBl + ko);
        }

        u32 Ahf[4][4];
        u32 Alf[4][4];
        u32 Bhf[2][4];
        u32 Blf[2][4];
        #pragma unroll
        for (int mt = 0; mt < 4; mt++) {
            LDM4(Ahf[mt], sbase + st + offA[mt]);
            LDM4(Alf[mt], sbase + st + offA[mt] + BUF_A_L);
        }
        #pragma unroll
        for (int bt = 0; bt < 2; bt++) {
            LDM4(Bhf[bt], sbase + st + offB[bt]);
            LDM4(Blf[bt], sbase + st + offB[bt] + (BUF_B_L - BUF_B_H));
        }
        #pragma unroll
        for (int mt = 0; mt < 4; mt++) {
            #pragma unroll
            for (int nt = 0; nt < 4; nt++) {
                const int bt = nt >> 1, sel = (nt & 1) * 2;
                MMA(c[mt][nt], Ahf[mt], Bhf[bt][sel], Bhf[bt][sel+1]);
                MMA(c[mt][nt], Ahf[mt], Blf[bt][sel], Blf[bt][sel+1]);
                MMA(c[mt][nt], Alf[mt], Bhf[bt][sel], Bhf[bt][sel+1]);
            }
        }

        if (more) {
            char* d = smem + ((kt + 1) & 1) * STAGE + sts_off;
            *(uint4*)(d + BUF_A_H) = nA;
            *(uint4*)(d + BUF_A_L) = nB;
            *(uint4*)(d + BUF_B_H) = nC;
            *(uint4*)(d + BUF_B_L) = nD;
        }
        __syncthreads();
    }

    // epilogue
    const int r0 = bm + wm*64 + (lane >> 2);
    const int cbase = bn + wn*32 + (lane & 3) * 2;
    #pragma unroll
    for (int mt = 0; mt < 4; mt++) {
        #pragma unroll
        for (int nt = 0; nt < 4; nt++) {
            const int col = cbase + nt*8;
            #pragma unroll
            for (int h2 = 0; h2 < 2; h2++) {
                const long r = r0 + mt*16 + h2*8;
                float v0 = c[mt][nt][h2*2], v1 = c[mt][nt][h2*2+1];
                if (epi >= 2) {
                    v0 = tanhf(v0 + bias[col]);
                    v1 = tanhf(v1 + bias[col+1]);
                }
                if (epi == 1 || epi == 3) {
                    const float2 av = *(const float2*)(addsrc + r*(long)ldadd + col);
                    v0 += av.x; v1 += av.y;
                }
                if (epi == 2) {
                    bf16 h0,l0,h1,l1;
                    split1(v0,h0,l0); split1(v1,h1,l1);
                    bf162 hh; hh.x=h0; hh.y=h1;
                    bf162 lo2; lo2.x=l0; lo2.y=l1;
                    *(bf162*)(Oh + r*(long)ldo + col) = hh;
                    *(bf162*)(Ol + r*(long)ldo + col) = lo2;
                } else {
                    float2 o; o.x = v0; o.y = v1;
                    *(float2*)(C + r*(long)ldc + col) = o;
                }
            }
        }
    }
}

// ---------------- host ----------------
static float *p_q, *p_k, *p_v, *p_out1;
static bf16 *p_xs_h, *p_xs_l, *p_cc_h, *p_cc_l, *p_ln2_h, *p_ln2_l, *p_h_h, *p_h_l;
static bf16 *p_wq_h,*p_wq_l,*p_wk_h,*p_wk_l,*p_wv_h,*p_wv_l,*p_wo_h,*p_wo_l;
static bf16 *p_f1w1_h,*p_f1w1_l,*p_f1w2_h,*p_f1w2_l,*p_f2w1_h,*p_f2w1_l,*p_f2w2_h,*p_f2w2_l;
static bool g_init = false;

static void split_launch(const float* w, bf16* h, bf16* l, int n) {
    int n4 = n / 4;
    split_kernel<<<(n4 + 255) / 256, 256>>>(w, h, l, n4);
}

extern "C" void kernel_launch(void* const* d_in, const int* in_sizes, int n_in,
                              void* d_out, int out_size)
{
    if (!g_init) {
        cudaGetSymbolAddress((void**)&p_q,    g_q);
        cudaGetSymbolAddress((void**)&p_k,    g_k);
        cudaGetSymbolAddress((void**)&p_v,    g_v);
        cudaGetSymbolAddress((void**)&p_out1, g_out1);
        cudaGetSymbolAddress((void**)&p_xs_h, g_xs_h);
        cudaGetSymbolAddress((void**)&p_xs_l, g_xs_l);
        cudaGetSymbolAddress((void**)&p_cc_h, g_cc_h);
        cudaGetSymbolAddress((void**)&p_cc_l, g_cc_l);
        cudaGetSymbolAddress((void**)&p_ln2_h,g_ln2_h);
        cudaGetSymbolAddress((void**)&p_ln2_l,g_ln2_l);
        cudaGetSymbolAddress((void**)&p_h_h,  g_h_h);
        cudaGetSymbolAddress((void**)&p_h_l,  g_h_l);
        cudaGetSymbolAddress((void**)&p_wq_h, g_wq_h);  cudaGetSymbolAddress((void**)&p_wq_l, g_wq_l);
        cudaGetSymbolAddress((void**)&p_wk_h, g_wk_h);  cudaGetSymbolAddress((void**)&p_wk_l, g_wk_l);
        cudaGetSymbolAddress((void**)&p_wv_h, g_wv_h);  cudaGetSymbolAddress((void**)&p_wv_l, g_wv_l);
        cudaGetSymbolAddress((void**)&p_wo_h, g_wo_h);  cudaGetSymbolAddress((void**)&p_wo_l, g_wo_l);
        cudaGetSymbolAddress((void**)&p_f1w1_h, g_f1w1_h); cudaGetSymbolAddress((void**)&p_f1w1_l, g_f1w1_l);
        cudaGetSymbolAddress((void**)&p_f1w2_h, g_f1w2_h); cudaGetSymbolAddress((void**)&p_f1w2_l, g_f1w2_l);
        cudaGetSymbolAddress((void**)&p_f2w1_h, g_f2w1_h); cudaGetSymbolAddress((void**)&p_f2w1_l, g_f2w1_l);
        cudaGetSymbolAddress((void**)&p_f2w2_h, g_f2w2_h); cudaGetSymbolAddress((void**)&p_f2w2_l, g_f2w2_l);
        g_init = true;
    }
    const float* input = (const float*)d_in[0];
    const float* Wq    = (const float*)d_in[1];
    const float* Wk    = (const float*)d_in[2];
    const float* Wv    = (const float*)d_in[3];
    const float* Wo    = (const float*)d_in[4];
    const float* ln1w  = (const float*)d_in[5];
    const float* ln1b  = (const float*)d_in[6];
    const float* ln2w  = (const float*)d_in[7];
    const float* ln2b  = (const float*)d_in[8];
    const float* f1w1  = (const float*)d_in[9];
    const float* f1b1  = (const float*)d_in[10];
    const float* f1w2  = (const float*)d_in[11];
    const float* f1b2  = (const float*)d_in[12];
    const float* f2w1  = (const float*)d_in[13];
    const float* f2b1  = (const float*)d_in[14];
    const float* f2w2  = (const float*)d_in[15];
    const float* f2b2  = (const float*)d_in[16];
    float* out = (float*)d_out;

    // weight splits
    split_launch(Wq, p_wq_h, p_wq_l, EMB*EMB);
    split_launch(Wk, p_wk_h, p_wk_l, EMB*EMB);
    split_launch(Wv, p_wv_h, p_wv_l, EMB*EMB);
    split_launch(Wo, p_wo_h, p_wo_l, EMB*EMB);
    split_launch(f1w1, p_f1w1_h, p_f1w1_l, HID*EMB);
    split_launch(f1w2, p_f1w2_h, p_f1w2_l, HID*EMB);
    split_launch(f2w1, p_f2w1_h, p_f2w1_l, HID*EMB);
    split_launch(f2w2, p_f2w2_h, p_f2w2_l, HID*EMB);

    // 1. LN1 -> xs (bf16 split)
    ln_kernel<<<BATCH, 256>>>(input, ln1w, ln1b, p_xs_h, p_xs_l);

    // 2. QKV projections
    dim3 blk(256);
    dim3 gq(EMB/128, MROWS/128);
    gemm_bf3<<<gq, blk>>>(p_xs_h, p_xs_l, EMB, p_wq_h, p_wq_l, EMB, nullptr,
                          p_q, EMB, nullptr, 0, nullptr, nullptr, 0, EMB, 0);
    gemm_bf3<<<gq, blk>>>(p_xs_h, p_xs_l, EMB, p_wk_h, p_wk_l, EMB, nullptr,
                          p_k, EMB, nullptr, 0, nullptr, nullptr, 0, EMB, 0);
    gemm_bf3<<<gq, blk>>>(p_xs_h, p_xs_l, EMB, p_wv_h, p_wv_l, EMB, nullptr,
                          p_v, EMB, nullptr, 0, nullptr, nullptr, 0, EMB, 0);

    // 3. attention -> cc (bf16 split)
    attn_kernel<<<BATCH, 512>>>(p_q, p_k, p_v, p_cc_h, p_cc_l);

    // 4. Wo + residual -> out1 (fp32)
    gemm_bf3<<<gq, blk>>>(p_cc_h, p_cc_l, EMB, p_wo_h, p_wo_l, EMB, nullptr,
                          p_out1, EMB, input, EMB, nullptr, nullptr, 0, EMB, 1);

    // 5. LN2 -> ln2 (bf16 split)
    ln_kernel<<<BATCH, 256>>>(p_out1, ln2w, ln2b, p_ln2_h, p_ln2_l);

    // 6. FFN layer 1 per s: h_s = tanh(ln2_s @ w1^T + b1) (bf16 split out)
    dim3 gf1(HID/128, BATCH/128);
    gemm_bf3<<<gf1, blk>>>(p_ln2_h,       p_ln2_l,       2*EMB, p_f1w1_h, p_f1w1_l, EMB, f1b1,
                           nullptr, 0, nullptr, 0, p_h_h, p_h_l, HID, EMB, 2);
    gemm_bf3<<<gf1, blk>>>(p_ln2_h + EMB, p_ln2_l + EMB, 2*EMB, p_f2w1_h, p_f2w1_l, EMB, f2b1,
                           nullptr, 0, nullptr, 0, p_h_h + (long)BATCH*HID, p_h_l + (long)BATCH*HID, HID, EMB, 2);

    // 7. FFN layer 2 per s + final residual -> out (fp32)
    dim3 gf2(EMB/128, BATCH/128);
    gemm_bf3<<<gf2, blk>>>(p_h_h,                   p_h_l,                   HID, p_f1w2_h, p_f1w2_l, HID, f1b2,
                           out,       2*EMB, p_out1,       2*EMB, nullptr, nullptr, 0, HID, 3);
    gemm_bf3<<<gf2, blk>>>(p_h_h + (long)BATCH*HID, p_h_l + (long)BATCH*HID, HID, p_f2w2_h, p_f2w2_l, HID, f2b2,
                           out + EMB, 2*EMB, p_out1 + EMB, 2*EMB, nullptr, nullptr, 0, HID, 3);
}